// round 13
// baseline (speedup 1.0000x reference)
#include <cuda_runtime.h>
#include <cuda_bf16.h>

// 1 CTA per TWO images (img, img+1024), grid 1024, 256 threads.
// Cross-image software pipeline: img1's 6 row LDGs are issued BEFORE img0's
// reduction barrier, hiding barrier+epilogue under load latency.
// Per-warp coeffs (lanes 0-8 load+clamp, shfl broadcast) - no barrier.
// Thread t: col quad q=t&15 (cols 4q..4q+3), rows 4*(t>>4)..+3.
// |gx|+|gy| == max(|conv(S)|, |conv(D)|), S=wr+wr^T, D=wr-wr^T.
// Warp min/max via redux.sync.u32 on float bits (g >= 0); cross-warp via
// parity-split smem atomics (cells[0,1]=img0 min/max, cells[2,3]=img1).

#define FULL 0xffffffffu
#define GRID 1024

__global__ __launch_bounds__(256, 4)
void sobel_norm_kernel(const float* __restrict__ in,
                       const float* __restrict__ w,
                       const float* __restrict__ wf,
                       const float* __restrict__ scale_p,
                       float* __restrict__ out) {
    __shared__ unsigned cells[4];   // {mn0, mx0, mn1, mx1}

    const int tid = threadIdx.x;
    const int lane = tid & 31;
    const int q   = tid & 15;        // col quad 0..15
    const int r0  = (tid >> 4) << 2; // first output row (0..60)
    const int c0  = q << 2;

    if (tid == 0) {
        cells[0] = 0x7f800000u; cells[1] = 0u;
        cells[2] = 0x7f800000u; cells[3] = 0u;
    }
    __syncthreads();   // orders init before both phases' atomics

    const size_t off = (size_t)(r0 << 6) + c0;
    const float* __restrict__ base0 = in + (size_t)blockIdx.x * 4096 + off;
    const float* __restrict__ base1 = base0 + (size_t)GRID * 4096;

    const bool topOK = (r0 != 0);
    const bool botOK = (r0 != 60);

    auto load6 = [&](const float* __restrict__ b, float4* m) {
        m[0] = topOK ? *reinterpret_cast<const float4*>(b - 64)
                     : make_float4(0.f, 0.f, 0.f, 0.f);
        m[1] = *reinterpret_cast<const float4*>(b);
        m[2] = *reinterpret_cast<const float4*>(b + 64);
        m[3] = *reinterpret_cast<const float4*>(b + 128);
        m[4] = *reinterpret_cast<const float4*>(b + 192);
        m[5] = botOK ? *reinterpret_cast<const float4*>(b + 256)
                     : make_float4(0.f, 0.f, 0.f, 0.f);
    };

    // ---- img0 loads first (MLP=6) ----
    float4 m0[6];
    load6(base0, m0);

    // ---- Per-warp coefficients, hidden under img0 LDGs ----
    float wv = 0.f;
    if (lane < 9) {
        const float f = fminf(fmaxf(__ldg(wf), 1.0f), 255.0f);
        wv = fminf(fmaxf(__ldg(w + lane), -1.0f), 1.0f) * f;
    }
    const float w0 = __shfl_sync(FULL, wv, 0);
    const float w1 = __shfl_sync(FULL, wv, 1);
    const float w2 = __shfl_sync(FULL, wv, 2);
    const float w3 = __shfl_sync(FULL, wv, 3);
    const float w4 = __shfl_sync(FULL, wv, 4);
    const float w5 = __shfl_sync(FULL, wv, 5);
    const float w6 = __shfl_sync(FULL, wv, 6);
    const float w7 = __shfl_sync(FULL, wv, 7);
    const float w8 = __shfl_sync(FULL, wv, 8);

    const float s00 = w0 + w0, s11 = w4 + w4, s22 = w8 + w8;
    const float s01 = w1 + w3, s02 = w2 + w6, s12 = w5 + w7;
    const float d01 = w1 - w3, d02 = w2 - w6, d12 = w5 - w7;
    const float sc  = __ldg(scale_p);

    auto expand = [&](float4 m, float* V) {
        float lf = __shfl_up_sync(FULL, m.w, 1);
        float rg = __shfl_down_sync(FULL, m.x, 1);
        if (q == 0)  lf = 0.f;
        if (q == 15) rg = 0.f;
        V[0] = lf;
        V[1] = m.x; V[2] = m.y; V[3] = m.z; V[4] = m.w;
        V[5] = rg;
    };

    // conv over one image's 6 preloaded rows -> g[16], thread-local min/max
    auto convimg = [&](const float4* m, float* g, float& gmn, float& gmx) {
        float W[3][6];
        gmn = 3.4e38f;
        gmx = 0.0f;   // g >= 0
        expand(m[0], W[0]);
        expand(m[1], W[1]);
#pragma unroll
        for (int i = 0; i < 4; i++) {
            expand(m[i + 2], W[(i + 2) % 3]);
            const float* a = W[i % 3];
            const float* b = W[(i + 1) % 3];
            const float* c = W[(i + 2) % 3];
#pragma unroll
            for (int p = 0; p < 4; p++) {
                const float a0 = a[p], a1 = a[p + 1], a2 = a[p + 2];
                const float b0 = b[p], b1 = b[p + 1], b2 = b[p + 2];
                const float c1 = c[p], c2 = c[p + 1], c3 = c[p + 2];
                float S = s00 * a0;
                S = fmaf(s11, b1, S);
                S = fmaf(s22, c3, S);
                S = fmaf(s01, a1 + b0, S);
                S = fmaf(s02, a2 + c1, S);
                S = fmaf(s12, b2 + c2, S);
                float D = d01 * (a1 - b0);
                D = fmaf(d02, a2 - c1, D);
                D = fmaf(d12, b2 - c2, D);
                const float gv = fmaxf(fabsf(S), fabsf(D));
                g[i * 4 + p] = gv;
                gmn = fminf(gmn, gv);
                gmx = fmaxf(gmx, gv);
            }
        }
    };

    auto reduce_in = [&](float gmn, float gmx, int cell) {
        unsigned wmn_u, wmx_u;
        asm("redux.sync.min.u32 %0, %1, 0xffffffff;" : "=r"(wmn_u) : "r"(__float_as_uint(gmn)));
        asm("redux.sync.max.u32 %0, %1, 0xffffffff;" : "=r"(wmx_u) : "r"(__float_as_uint(gmx)));
        if (lane == 0) {
            atomicMin(&cells[cell], wmn_u);
            atomicMax(&cells[cell + 1], wmx_u);
        }
    };

    auto epilogue = [&](float* __restrict__ op, const float* g, int cell) {
        const float gmn = __uint_as_float(cells[cell]);
        const float gmx = __uint_as_float(cells[cell + 1]);
        const float mul = 255.0f / fmaxf(gmx - gmn, 1.0f);
        const float nb  = -gmn * mul;
        if (sc == 1.0f) {
#pragma unroll
            for (int i = 0; i < 4; i++) {
                float4 o4;
                o4.x = floorf(fmaf(g[i * 4 + 0], mul, nb));
                o4.y = floorf(fmaf(g[i * 4 + 1], mul, nb));
                o4.z = floorf(fmaf(g[i * 4 + 2], mul, nb));
                o4.w = floorf(fmaf(g[i * 4 + 3], mul, nb));
                *reinterpret_cast<float4*>(op + (i << 6)) = o4;
            }
        } else {
            const float isc = 1.0f / sc;
#pragma unroll
            for (int i = 0; i < 4; i++) {
                float4 o4;
                o4.x = floorf(fmaf(g[i * 4 + 0], mul, nb)) * isc;
                o4.y = floorf(fmaf(g[i * 4 + 1], mul, nb)) * isc;
                o4.z = floorf(fmaf(g[i * 4 + 2], mul, nb)) * isc;
                o4.w = floorf(fmaf(g[i * 4 + 3], mul, nb)) * isc;
                *reinterpret_cast<float4*>(op + (i << 6)) = o4;
            }
        }
    };

    float g[16], gmn, gmx;

    // ---- Phase 0: conv img0, start img1 loads BEFORE the barrier ----
    convimg(m0, g, gmn, gmx);
    reduce_in(gmn, gmx, 0);

    float4 m1[6];
    load6(base1, m1);           // in flight across barrier + epilogue0

    __syncthreads();
    epilogue(out + (size_t)blockIdx.x * 4096 + off, g, 0);

    // ---- Phase 1: conv img1 (loads have had barrier+epilogue to arrive) ----
    convimg(m1, g, gmn, gmx);
    reduce_in(gmn, gmx, 2);
    __syncthreads();
    epilogue(out + (size_t)(blockIdx.x + GRID) * 4096 + off, g, 2);
}

extern "C" void kernel_launch(void* const* d_in, const int* in_sizes, int n_in,
                              void* d_out, int out_size) {
    const float* in      = (const float*)d_in[0];  // (2048,1,64,64) fp32
    const float* w       = (const float*)d_in[1];  // (1,9) fp32
    const float* wf      = (const float*)d_in[2];  // (1,) fp32
    const float* scale_p = (const float*)d_in[3];  // (1,1) fp32
    float* out = (float*)d_out;                    // (1,2048,1,64,64) fp32
    (void)in_sizes; (void)n_in; (void)out_size;

    sobel_norm_kernel<<<GRID, 256>>>(in, w, wf, scale_p, out);
}